// round 15
// baseline (speedup 1.0000x reference)
#include <cuda_runtime.h>

#define NROWS 14400   // bs * Q
#define NCLS  128
#define NTGT  3200
#define BT    128     // targets per block
#define BR    32      // rows per block
#define RBLK  450     // NROWS / BR
#define CPAD  36      // padded row stride (floats) of transposed cc table

typedef unsigned long long u64;

// Scratch (no allocations allowed) ------------------------------------------
__device__ __align__(16) float   g_ccostT[NROWS * NCLS]; // [450][128 cls][32 rows], (+2 folded)
__device__ __align__(16) float4  g_tcwh[NTGT];           // cx,cy,w,h
__device__ __align__(16) float4  g_txyxy[NTGT];          // x0,y0,x1,y1
__device__ __align__(8)  ushort4 g_toff4[NTGT / 4];      // cls*144 byte-offsets per target-quad

// ---- packed f32x2 helpers (sm_103a: add/sub/mul/fma only) ------------------
__device__ __forceinline__ u64 pk2(float lo, float hi) {
    u64 r; asm("mov.b64 %0,{%1,%2};" : "=l"(r) : "f"(lo), "f"(hi)); return r;
}
__device__ __forceinline__ float2 upk2(u64 v) {
    float2 f; asm("mov.b64 {%0,%1},%2;" : "=f"(f.x), "=f"(f.y) : "l"(v)); return f;
}
__device__ __forceinline__ u64 padd(u64 a, u64 b) {
    u64 r; asm("add.rn.f32x2 %0,%1,%2;" : "=l"(r) : "l"(a), "l"(b)); return r;
}
__device__ __forceinline__ u64 psub(u64 a, u64 b) {
    u64 r; asm("sub.rn.f32x2 %0,%1,%2;" : "=l"(r) : "l"(a), "l"(b)); return r;
}
__device__ __forceinline__ float frcp(float x) {
    float r; asm("rcp.approx.f32 %0,%1;" : "=f"(r) : "f"(x)); return r;
}

__device__ __forceinline__ float focal_cc2(float p) {
    float ip  = 1.0f - p;
    float pos = 0.25f * ip * ip * (-__logf(p  + 1e-8f));
    float neg = 0.75f * p  * p  * (-__logf(ip + 1e-8f));
    return pos - neg + 2.0f;          // +2 from GIoU algebra folded in
}

// ---------------------------------------------------------------------------
// Kernel 1: blocks [0,450): 32 warps = 32 rows; softmax + focal table,
// transposed through smem, written coalesced as [class][row-in-block].
// Block 450: target precompute (cwh, xyxy, pre-scaled class offsets).
// ---------------------------------------------------------------------------
__global__ void __launch_bounds__(1024)
prep(const float* __restrict__ logits,
     const float* __restrict__ tbox,
     const int*   __restrict__ tids) {
    if (blockIdx.x < RBLK) {
        __shared__ float s_t[NCLS * 33];   // [class][row] padded
        int w    = threadIdx.x >> 5;       // warp = row-in-block
        int lane = threadIdx.x & 31;
        int row  = blockIdx.x * BR + w;

        float4 l = ((const float4*)(logits + (size_t)row * NCLS))[lane];

        float m = fmaxf(fmaxf(l.x, l.y), fmaxf(l.z, l.w));
        #pragma unroll
        for (int o = 16; o > 0; o >>= 1) m = fmaxf(m, __shfl_xor_sync(0xffffffffu, m, o));

        float ex = __expf(l.x - m), ey = __expf(l.y - m);
        float ez = __expf(l.z - m), ew = __expf(l.w - m);
        float s = ex + ey + ez + ew;
        #pragma unroll
        for (int o = 16; o > 0; o >>= 1) s += __shfl_xor_sync(0xffffffffu, s, o);
        float rs = __fdividef(1.0f, s);

        int c0 = lane * 4;
        s_t[(c0 + 0) * 33 + w] = focal_cc2(ex * rs);
        s_t[(c0 + 1) * 33 + w] = focal_cc2(ey * rs);
        s_t[(c0 + 2) * 33 + w] = focal_cc2(ez * rs);
        s_t[(c0 + 3) * 33 + w] = focal_cc2(ew * rs);
        __syncthreads();

        // coalesced write-out: float4 over rows, class-major
        int tid = threadIdx.x;
        int c  = tid >> 3;
        int r0 = (tid & 7) * 4;
        const float* p = s_t + c * 33 + r0;
        float4 v = make_float4(p[0], p[1], p[2], p[3]);
        ((float4*)g_ccostT)[(size_t)blockIdx.x * 1024 + tid] = v;
    } else {
        int t4 = threadIdx.x;
        if (t4 < NTGT / 4) {
            int4 ids = ((const int4*)tids)[t4];
            ushort4 off;
            off.x = (unsigned short)(min(max(ids.x, 0), NCLS - 1) * (CPAD * 4));
            off.y = (unsigned short)(min(max(ids.y, 0), NCLS - 1) * (CPAD * 4));
            off.z = (unsigned short)(min(max(ids.z, 0), NCLS - 1) * (CPAD * 4));
            off.w = (unsigned short)(min(max(ids.w, 0), NCLS - 1) * (CPAD * 4));
            g_toff4[t4] = off;
            #pragma unroll
            for (int m = 0; m < 4; m++) {
                float4 b = ((const float4*)tbox)[t4 * 4 + m];
                g_tcwh[t4 * 4 + m] = b;
                float hw = 0.5f * b.z, hh = 0.5f * b.w;
                g_txyxy[t4 * 4 + m] =
                    make_float4(b.x - hw, b.y - hh, b.x + hw, b.y + hh);
            }
        }
    }
}

// ---------------------------------------------------------------------------
// Kernel 2: main cost matrix. Grid (25, 450), 256 threads.
// tx = tid&31 -> 4 contiguous targets (STG.128); ty = tid>>5 -> 4 rows.
// R12 structure + packed add/sub for L1 diffs and wh-sum (alias-free packs).
// ---------------------------------------------------------------------------
__global__ void __launch_bounds__(256, 4)
cost_main(const float* __restrict__ pboxes,
          float* __restrict__ out) {
    __shared__ float   s_cc[NCLS * CPAD];  // 18.4 KB, [class][row] pad-36
    __shared__ float4  s_tcJ[BT];          // cwh, j-major: [j][tx]
    __shared__ float4  s_txJ[BT];          // xyxy, j-major: [j][tx]
    __shared__ ushort4 s_toff[BT / 4];     // pre-scaled cc byte-offsets

    int tid = threadIdx.x;
    int tb  = blockIdx.x * BT;
    int rb  = blockIdx.y;                   // 32-row block index

    // Stage transposed cc table: 1024 float4, 4 per thread, conflict-free STS
    {
        const float4* src = (const float4*)g_ccostT + (size_t)rb * 1024;
        #pragma unroll
        for (int k = 0; k < 4; k++) {
            int f  = tid + k * 256;
            int c  = f >> 3;
            int rq = f & 7;
            *(float4*)(s_cc + c * CPAD + rq * 4) = src[f];
        }
    }
    // Stage targets j-major: target t = 4*tx + j  ->  slot j*32 + tx
    if (tid < BT) {
        int slot = (tid & 3) * 32 + (tid >> 2);
        s_tcJ[slot] = g_tcwh[tb + tid];
        s_txJ[slot] = g_txyxy[tb + tid];
    }
    if (tid < BT / 4) s_toff[tid] = g_toff4[(tb >> 2) + tid];
    __syncthreads();

    int tx = tid & 31, ty = tid >> 5;
    int r0 = rb * BR + ty * 4;

    // Row operands (persistent): xyxy scalar for FMNMX, cc/wh packed for psub
    float rx0[4], ry0[4], rx1[4], ry1[4], ra[4];
    u64   rcc[4], rwh[4];
    #pragma unroll
    for (int i = 0; i < 4; i++) {
        float4 b = ((const float4*)pboxes)[r0 + i];
        rcc[i] = pk2(b.x, b.y);
        rwh[i] = pk2(b.z, b.w);
        float hw = 0.5f * b.z, hh = 0.5f * b.w;
        rx0[i] = b.x - hw; ry0[i] = b.y - hh;
        rx1[i] = b.x + hw; ry1[i] = b.y + hh;
        ra[i]  = b.z * b.w;
    }

    float o[4][4];
    ushort4 ofs = s_toff[tx];
    int offB[4] = {ofs.x, ofs.y, ofs.z, ofs.w};
    const char* ccbase = (const char*)(s_cc + ty * 4);   // hoisted row offset

    #pragma unroll
    for (int j = 0; j < 4; j++) {
        // Target operands (lane-contiguous conflict-free LDS.128)
        float4 c = s_tcJ[j * 32 + tx];
        float4 x = s_txJ[j * 32 + tx];
        u64 tcc = pk2(c.x, c.y);            // aligned float4 halves: free alias
        u64 twh = pk2(c.z, c.w);
        float ta = c.z * c.w;

        // class cost (+2) for all 4 rows: one LDS.128 at base + pre-scaled offset
        float4 ccv = *(const float4*)(ccbase + offB[j]);
        const float* ccp = &ccv.x;

        #pragma unroll
        for (int i = 0; i < 4; i++) {
            // L1: packed diffs, abs folded into the scalar add tree
            float2 d1 = upk2(psub(rcc[i], tcc));
            float2 d2 = upk2(psub(rwh[i], twh));
            float l1 = (fabsf(d1.x) + fabsf(d1.y)) + (fabsf(d2.x) + fabsf(d2.y));

            // intersection span (scalar FMNMX; may be negative)
            float ltx = fmaxf(rx0[i], x.x);
            float lty = fmaxf(ry0[i], x.y);
            float rbx = fminf(rx1[i], x.z);
            float rby = fminf(ry1[i], x.w);
            float sx  = rbx - ltx;
            float sy  = rby - lty;
            float inter = fmaxf(sx, 0.0f) * fmaxf(sy, 0.0f);

            // enclosure identity: encl = (w_r + w_t) - span; wh-sum packed
            float2 ws = upk2(padd(rwh[i], twh));
            float ex = ws.x - sx;
            float ey = ws.y - sy;
            float ai = ex * ey;

            float uni = (ra[i] + ta) - inter;

            // C = 5*l1 + (cc+2) - 2*(inter/uni + uni/ai)
            float iou = inter * frcp(uni);
            float q   = uni * frcp(ai);
            float t2  = iou + q;
            float res = fmaf(l1, 5.0f, ccp[i]);  // FFMA-imm
            res = fmaf(t2, -2.0f, res);          // FFMA-imm
            o[i][j] = res;
        }
    }

    #pragma unroll
    for (int i = 0; i < 4; i++) {
        float4 v = make_float4(o[i][0], o[i][1], o[i][2], o[i][3]);
        *((float4*)(out + (size_t)(r0 + i) * NTGT + tb + tx * 4)) = v;
    }
}

// ---------------------------------------------------------------------------
extern "C" void kernel_launch(void* const* d_in, const int* in_sizes, int n_in,
                              void* d_out, int out_size) {
    const float* logits = (const float*)d_in[0];      // [16,900,128]
    const float* pboxes = (const float*)d_in[1];      // [16,900,4]
    const int*   tids   = (const int*)d_in[2];        // [3200] int32
    const float* tbox   = (const float*)d_in[3];      // [3200,4]
    float* out = (float*)d_out;                       // [16,900,3200]

    prep<<<RBLK + 1, 1024>>>(logits, tbox, tids);

    dim3 grid(NTGT / BT, RBLK);                       // (25, 450)
    cost_main<<<grid, 256>>>(pboxes, out);
}

// round 16
// speedup vs baseline: 1.1481x; 1.1481x over previous
#include <cuda_runtime.h>

#define NROWS 14400   // bs * Q
#define NCLS  128
#define NTGT  3200
#define BT    128     // targets per block
#define BR    32      // rows per block
#define RBLK  450     // NROWS / BR
#define CPAD  36      // padded row stride (floats) of transposed cc table

// Scratch (no allocations allowed) ------------------------------------------
__device__ __align__(16) float   g_ccostT[NROWS * NCLS]; // [450][128 cls][32 rows], (+2 folded)
__device__ __align__(16) float4  g_tcwh[NTGT];           // cx,cy,w,h
__device__ __align__(16) float4  g_txyxy[NTGT];          // x0,y0,x1,y1
__device__ __align__(8)  ushort4 g_toff4[NTGT / 4];      // cls*144 byte-offsets per target-quad

__device__ __forceinline__ float frcp(float x) {
    float r; asm("rcp.approx.f32 %0,%1;" : "=f"(r) : "f"(x)); return r;
}

__device__ __forceinline__ float focal_cc2(float p) {
    float ip  = 1.0f - p;
    float pos = 0.25f * ip * ip * (-__logf(p  + 1e-8f));
    float neg = 0.75f * p  * p  * (-__logf(ip + 1e-8f));
    return pos - neg + 2.0f;          // +2 from GIoU algebra folded in
}

// ---------------------------------------------------------------------------
// Kernel 1: blocks [0,450): 32 warps = 32 rows; softmax + focal table,
// transposed through smem, written coalesced as [class][row-in-block].
// Block 450: target precompute (cwh, xyxy, pre-scaled class offsets).
// ---------------------------------------------------------------------------
__global__ void __launch_bounds__(1024)
prep(const float* __restrict__ logits,
     const float* __restrict__ tbox,
     const int*   __restrict__ tids) {
    if (blockIdx.x < RBLK) {
        __shared__ float s_t[NCLS * 33];   // [class][row] padded
        int w    = threadIdx.x >> 5;       // warp = row-in-block
        int lane = threadIdx.x & 31;
        int row  = blockIdx.x * BR + w;

        float4 l = ((const float4*)(logits + (size_t)row * NCLS))[lane];

        float m = fmaxf(fmaxf(l.x, l.y), fmaxf(l.z, l.w));
        #pragma unroll
        for (int o = 16; o > 0; o >>= 1) m = fmaxf(m, __shfl_xor_sync(0xffffffffu, m, o));

        float ex = __expf(l.x - m), ey = __expf(l.y - m);
        float ez = __expf(l.z - m), ew = __expf(l.w - m);
        float s = ex + ey + ez + ew;
        #pragma unroll
        for (int o = 16; o > 0; o >>= 1) s += __shfl_xor_sync(0xffffffffu, s, o);
        float rs = __fdividef(1.0f, s);

        int c0 = lane * 4;
        s_t[(c0 + 0) * 33 + w] = focal_cc2(ex * rs);
        s_t[(c0 + 1) * 33 + w] = focal_cc2(ey * rs);
        s_t[(c0 + 2) * 33 + w] = focal_cc2(ez * rs);
        s_t[(c0 + 3) * 33 + w] = focal_cc2(ew * rs);
        __syncthreads();

        // coalesced write-out: float4 over rows, class-major
        int tid = threadIdx.x;
        int c  = tid >> 3;
        int r0 = (tid & 7) * 4;
        const float* p = s_t + c * 33 + r0;
        float4 v = make_float4(p[0], p[1], p[2], p[3]);
        ((float4*)g_ccostT)[(size_t)blockIdx.x * 1024 + tid] = v;
    } else {
        int t4 = threadIdx.x;
        if (t4 < NTGT / 4) {
            int4 ids = ((const int4*)tids)[t4];
            ushort4 off;
            off.x = (unsigned short)(min(max(ids.x, 0), NCLS - 1) * (CPAD * 4));
            off.y = (unsigned short)(min(max(ids.y, 0), NCLS - 1) * (CPAD * 4));
            off.z = (unsigned short)(min(max(ids.z, 0), NCLS - 1) * (CPAD * 4));
            off.w = (unsigned short)(min(max(ids.w, 0), NCLS - 1) * (CPAD * 4));
            g_toff4[t4] = off;
            #pragma unroll
            for (int m = 0; m < 4; m++) {
                float4 b = ((const float4*)tbox)[t4 * 4 + m];
                g_tcwh[t4 * 4 + m] = b;
                float hw = 0.5f * b.z, hh = 0.5f * b.w;
                g_txyxy[t4 * 4 + m] =
                    make_float4(b.x - hw, b.y - hh, b.x + hw, b.y + hh);
            }
        }
    }
}

// ---------------------------------------------------------------------------
// Kernel 2: main cost matrix. Grid (25, 450), 256 threads.
// tx = tid&31 -> 4 contiguous targets (STG.128); ty = tid>>5 -> 4 rows.
// Transposed cc table: one LDS.128 = class cost for all 4 rows, addressed
// by a pre-scaled byte offset. Targets staged j-major (lane-contiguous).
// GIoU fractions combined over one reciprocal (1 MUFU instead of 2).
// ---------------------------------------------------------------------------
__global__ void __launch_bounds__(256, 4)
cost_main(const float* __restrict__ pboxes,
          float* __restrict__ out) {
    __shared__ float   s_cc[NCLS * CPAD];  // 18.4 KB, [class][row] pad-36
    __shared__ float4  s_tcJ[BT];          // cwh, j-major: [j][tx]
    __shared__ float4  s_txJ[BT];          // xyxy, j-major: [j][tx]
    __shared__ ushort4 s_toff[BT / 4];     // pre-scaled cc byte-offsets

    int tid = threadIdx.x;
    int tb  = blockIdx.x * BT;
    int rb  = blockIdx.y;                   // 32-row block index

    // Stage transposed cc table: 1024 float4, 4 per thread, conflict-free STS
    {
        const float4* src = (const float4*)g_ccostT + (size_t)rb * 1024;
        #pragma unroll
        for (int k = 0; k < 4; k++) {
            int f  = tid + k * 256;
            int c  = f >> 3;
            int rq = f & 7;
            *(float4*)(s_cc + c * CPAD + rq * 4) = src[f];
        }
    }
    // Stage targets j-major: target t = 4*tx + j  ->  slot j*32 + tx
    if (tid < BT) {
        int slot = (tid & 3) * 32 + (tid >> 2);
        s_tcJ[slot] = g_tcwh[tb + tid];
        s_txJ[slot] = g_txyxy[tb + tid];
    }
    if (tid < BT / 4) s_toff[tid] = g_toff4[(tb >> 2) + tid];
    __syncthreads();

    int tx = tid & 31, ty = tid >> 5;
    int r0 = rb * BR + ty * 4;

    // Row operands (persistent): 9 x 4 regs
    float rx0[4], ry0[4], rx1[4], ry1[4];
    float rcx[4], rcy[4], rw[4], rh[4], ra[4];
    #pragma unroll
    for (int i = 0; i < 4; i++) {
        float4 b = ((const float4*)pboxes)[r0 + i];
        rcx[i] = b.x; rcy[i] = b.y; rw[i] = b.z; rh[i] = b.w;
        float hw = 0.5f * b.z, hh = 0.5f * b.w;
        rx0[i] = b.x - hw; ry0[i] = b.y - hh;
        rx1[i] = b.x + hw; ry1[i] = b.y + hh;
        ra[i]  = b.z * b.w;
    }

    float o[4][4];
    ushort4 ofs = s_toff[tx];
    int offB[4] = {ofs.x, ofs.y, ofs.z, ofs.w};
    const char* ccbase = (const char*)(s_cc + ty * 4);   // hoisted row offset

    #pragma unroll
    for (int j = 0; j < 4; j++) {
        // Target operands (transient; lane-contiguous conflict-free LDS.128)
        float4 c = s_tcJ[j * 32 + tx];
        float4 x = s_txJ[j * 32 + tx];
        float ta = c.z * c.w;

        // class cost (+2) for all 4 rows: one LDS.128 at base + pre-scaled offset
        float4 ccv = *(const float4*)(ccbase + offB[j]);
        const float* ccp = &ccv.x;

        #pragma unroll
        for (int i = 0; i < 4; i++) {
            // L1 (cxcywh)
            float l1 = (fabsf(rcx[i] - c.x) + fabsf(rcy[i] - c.y))
                     + (fabsf(rw[i]  - c.z) + fabsf(rh[i]  - c.w));

            // intersection span (may be negative)
            float ltx = fmaxf(rx0[i], x.x);
            float lty = fmaxf(ry0[i], x.y);
            float rbx = fminf(rx1[i], x.z);
            float rby = fminf(ry1[i], x.w);
            float sx  = rbx - ltx;
            float sy  = rby - lty;
            float inter = fmaxf(sx, 0.0f) * fmaxf(sy, 0.0f);

            // enclosure via identity: encl = w_r + w_t - span
            float ex = (rw[i] + c.z) - sx;
            float ey = (rh[i] + c.w) - sy;
            float ai = ex * ey;

            float uni = (ra[i] + ta) - inter;

            // t2 = inter/uni + uni/ai = (inter*ai + uni^2) / (uni*ai)
            float den = uni * ai;
            float num = fmaf(uni, uni, inter * ai);
            float t2  = num * frcp(den);          // single MUFU.RCP

            // C = 5*l1 + (cc+2) - 2*t2
            float res = fmaf(l1, 5.0f, ccp[i]);   // FFMA-imm
            res = fmaf(t2, -2.0f, res);           // FFMA-imm
            o[i][j] = res;
        }
    }

    #pragma unroll
    for (int i = 0; i < 4; i++) {
        float4 v = make_float4(o[i][0], o[i][1], o[i][2], o[i][3]);
        *((float4*)(out + (size_t)(r0 + i) * NTGT + tb + tx * 4)) = v;
    }
}

// ---------------------------------------------------------------------------
extern "C" void kernel_launch(void* const* d_in, const int* in_sizes, int n_in,
                              void* d_out, int out_size) {
    const float* logits = (const float*)d_in[0];      // [16,900,128]
    const float* pboxes = (const float*)d_in[1];      // [16,900,4]
    const int*   tids   = (const int*)d_in[2];        // [3200] int32
    const float* tbox   = (const float*)d_in[3];      // [3200,4]
    float* out = (float*)d_out;                       // [16,900,3200]

    prep<<<RBLK + 1, 1024>>>(logits, tbox, tids);

    dim3 grid(NTGT / BT, RBLK);                       // (25, 450)
    cost_main<<<grid, 256>>>(pboxes, out);
}